// round 1
// baseline (speedup 1.0000x reference)
#include <cuda_runtime.h>

// Problem constants (fixed by setup_inputs)
#define H   80
#define B   4096
#define T   512
#define RPB 32              // rows (batch) per CTA
#define NCTA (B / RPB)      // 128
#define NTHR 320            // thread = (j in [0,80), rblk in [0,4))

// Packed weight layout (floats):
//   layer 1: k in [0,81)  : Wp[(k*80+j)*4 + g], k=0 -> x weight, k>=1 -> h1 weight (col k-1)
//   layer l>=2: k in [0,160): k<80 -> w_ih col k (input h_{l-1}), k>=80 -> w_hh col k-80 (own h)
#define OFF1 0
#define OFF2 25920          // 81*320
#define OFF3 77120          // OFF2 + 160*320
#define OFF4 128320
#define WTOT 179520
#define BTOT 1280           // 4 layers * 320 (bias, gate-interleaved [l][j][g])

__device__ float g_Wp[WTOT];
__device__ float g_Bp[BTOT];

typedef unsigned long long u64;

__device__ __forceinline__ u64 dup2(float w) {
    u64 r; unsigned u = __float_as_uint(w);
    asm("mov.b64 %0, {%1, %1};" : "=l"(r) : "r"(u));
    return r;
}
__device__ __forceinline__ void fma2(u64 &d, u64 a, u64 b) {
    asm("fma.rn.f32x2 %0, %1, %2, %0;" : "+l"(d) : "l"(a), "l"(b));
}
__device__ __forceinline__ float lo32(u64 v) { return __uint_as_float((unsigned)v); }
__device__ __forceinline__ float hi32(u64 v) { return __uint_as_float((unsigned)(v >> 32)); }

__device__ __forceinline__ float sigf(float x) {
    return __fdividef(1.0f, 1.0f + __expf(-x));
}
__device__ __forceinline__ float tanh_f(float x) {
    // tanh(x) = 2*sigmoid(2x) - 1
    return fmaf(2.0f, sigf(2.0f * x), -1.0f);
}

// One k-slice: 4 gate weights (float4) times h values for 8 rows -> 16 FFMA2
__device__ __forceinline__ void fmak(u64 *acc, float4 w, const float *hk) {
    u64 w0 = dup2(w.x), w1 = dup2(w.y), w2 = dup2(w.z), w3 = dup2(w.w);
    const ulonglong2 *hp = (const ulonglong2 *)hk;   // 16B aligned (r0 multiple of 8 floats)
    ulonglong2 ha = hp[0], hb = hp[1];
    fma2(acc[0],  w0, ha.x); fma2(acc[1],  w0, ha.y); fma2(acc[2],  w0, hb.x); fma2(acc[3],  w0, hb.y);
    fma2(acc[4],  w1, ha.x); fma2(acc[5],  w1, ha.y); fma2(acc[6],  w1, hb.x); fma2(acc[7],  w1, hb.y);
    fma2(acc[8],  w2, ha.x); fma2(acc[9],  w2, ha.y); fma2(acc[10], w2, hb.x); fma2(acc[11], w2, hb.y);
    fma2(acc[12], w3, ha.x); fma2(acc[13], w3, ha.y); fma2(acc[14], w3, hb.x); fma2(acc[15], w3, hb.y);
}

// 80-wide dot accumulation: W is float4[k][80] (gate-interleaved), hsrc is [k][32rows] in smem
__device__ __forceinline__ void gemm80(u64 *acc, const float4 *__restrict__ W,
                                       const float *__restrict__ hsrc, int j, int r0) {
#pragma unroll 4
    for (int k = 0; k < 80; k++) {
        fmak(acc, W[k * 80 + j], hsrc + k * RPB + r0);
    }
}

// LSTM elementwise: acc holds [gate(4)][rowpair(4)] packed f32x2; c is 8-row cell state (regs)
__device__ __forceinline__ void cell(const u64 *acc, float (&c)[8], float *hdst, int j, int r0) {
    float hv[8];
#pragma unroll
    for (int qq = 0; qq < 8; qq++) {
        int pp = qq >> 1;
        float iv, fv, gv, ov;
        if (qq & 1) {
            iv = hi32(acc[0 + pp]); fv = hi32(acc[4 + pp]);
            gv = hi32(acc[8 + pp]); ov = hi32(acc[12 + pp]);
        } else {
            iv = lo32(acc[0 + pp]); fv = lo32(acc[4 + pp]);
            gv = lo32(acc[8 + pp]); ov = lo32(acc[12 + pp]);
        }
        float cc = sigf(fv) * c[qq] + sigf(iv) * tanh_f(gv);
        c[qq] = cc;
        hv[qq] = sigf(ov) * tanh_f(cc);
    }
    float4 *d = (float4 *)(hdst + j * RPB + r0);
    d[0] = make_float4(hv[0], hv[1], hv[2], hv[3]);
    d[1] = make_float4(hv[4], hv[5], hv[6], hv[7]);
}

__device__ __forceinline__ void acc_init(u64 *acc, float4 b) {
    u64 b0 = dup2(b.x), b1 = dup2(b.y), b2 = dup2(b.z), b3 = dup2(b.w);
#pragma unroll
    for (int p = 0; p < 4; p++) { acc[0 + p] = b0; acc[4 + p] = b1; acc[8 + p] = b2; acc[12 + p] = b3; }
}

// ---------------------------------------------------------------------------
// Weight/bias repack kernel: transpose + gate-interleave into g_Wp / g_Bp
// ---------------------------------------------------------------------------
__global__ void pack_kernel(
    const float *wih1, const float *whh1, const float *bih1, const float *bhh1,
    const float *wih2, const float *whh2, const float *bih2, const float *bhh2,
    const float *wih3, const float *whh3, const float *bih3, const float *bhh3,
    const float *wih4, const float *whh4, const float *bih4, const float *bhh4) {
    int idx = blockIdx.x * blockDim.x + threadIdx.x;
    const float *wih[4] = {wih1, wih2, wih3, wih4};
    const float *whh[4] = {whh1, whh2, whh3, whh4};
    const float *bih[4] = {bih1, bih2, bih3, bih4};
    const float *bhh[4] = {bhh1, bhh2, bhh3, bhh4};
    if (idx < WTOT) {
        int l, off;
        if (idx < OFF2)      { l = 0; off = OFF1; }
        else if (idx < OFF3) { l = 1; off = OFF2; }
        else if (idx < OFF4) { l = 2; off = OFF3; }
        else                 { l = 3; off = OFF4; }
        int e = idx - off;
        int g = e & 3;
        int j = (e >> 2) % 80;
        int k = e / 320;
        int row = g * 80 + j;
        float v;
        if (l == 0) v = (k == 0) ? wih[0][row] : whh[0][row * 80 + (k - 1)];
        else        v = (k < 80) ? wih[l][row * 80 + k] : whh[l][row * 80 + (k - 80)];
        g_Wp[idx] = v;
    } else if (idx < WTOT + BTOT) {
        int e = idx - WTOT;
        int g = e & 3;
        int j = (e >> 2) % 80;
        int l = e / 320;
        int row = g * 80 + j;
        g_Bp[e] = bih[l][row] + bhh[l][row];
    }
}

// ---------------------------------------------------------------------------
// Main persistent LSTM kernel: each CTA owns 32 rows through all layers/steps
// ---------------------------------------------------------------------------
#define SMEM_FLOATS (4 * 2 * H * RPB + RPB + H)   // hs double-buffered + x_s + wlin_s
#define SMEM_BYTES  (SMEM_FLOATS * 4)

__global__ void __launch_bounds__(NTHR, 1) lstm4_kernel(
    const float *__restrict__ input,  // (B, T)
    const float *__restrict__ wlin,   // (80)
    const float *__restrict__ blin,   // (1)
    float *__restrict__ out) {        // (B, T)
    extern __shared__ float sm[];
    float *hs_base = sm;                          // [4][2][80][32]
    float *x_s     = sm + 4 * 2 * H * RPB;        // [32]
    float *wlin_s  = x_s + RPB;                   // [80]

    const int tid  = threadIdx.x;
    const int j    = tid % 80;
    const int rblk = tid / 80;
    const int r0   = rblk * 8;
    const int b0   = blockIdx.x * RPB;

    for (int i = tid; i < 4 * 2 * H * RPB; i += NTHR) hs_base[i] = 0.0f;
    if (tid < H) wlin_s[tid] = wlin[tid];
    const float blin_v = blin[0];

    const float4 *Bp4 = (const float4 *)g_Bp;
    float4 b1 = Bp4[0 * 80 + j], b2 = Bp4[1 * 80 + j], b3 = Bp4[2 * 80 + j], b4 = Bp4[3 * 80 + j];

    float c[4][8];
#pragma unroll
    for (int l = 0; l < 4; l++)
#pragma unroll
        for (int qq = 0; qq < 8; qq++) c[l][qq] = 0.0f;

    const float4 *W1 = (const float4 *)(g_Wp + OFF1);
    const float4 *W2 = (const float4 *)(g_Wp + OFF2);
    const float4 *W3 = (const float4 *)(g_Wp + OFF3);
    const float4 *W4 = (const float4 *)(g_Wp + OFF4);

    __syncthreads();

    for (int t = 0; t < T; t++) {
        const int p = t & 1;       // write buffer this step
        const int q = p ^ 1;       // own-h read buffer (previous step)
        float *h1n = hs_base + (0 * 2 + p) * H * RPB;
        const float *h1o = hs_base + (0 * 2 + q) * H * RPB;
        float *h2n = hs_base + (1 * 2 + p) * H * RPB;
        const float *h2o = hs_base + (1 * 2 + q) * H * RPB;
        float *h3n = hs_base + (2 * 2 + p) * H * RPB;
        const float *h3o = hs_base + (2 * 2 + q) * H * RPB;
        float *h4n = hs_base + (3 * 2 + p) * H * RPB;
        const float *h4o = hs_base + (3 * 2 + q) * H * RPB;

        if (tid < RPB) x_s[tid] = input[(b0 + tid) * T + t];
        __syncthreads();

        u64 acc[16];

        // ----- layer 1 (input: scalar x, own h1) -----
        acc_init(acc, b1);
        fmak(acc, W1[j], x_s + r0);            // k = 0: x weight
        gemm80(acc, W1 + 80, h1o, j, r0);      // k = 1..80: recurrent
        cell(acc, c[0], h1n, j, r0);
        __syncthreads();

        // ----- layer 2 -----
        acc_init(acc, b2);
        gemm80(acc, W2, h1n, j, r0);
        gemm80(acc, W2 + 80 * 80, h2o, j, r0);
        cell(acc, c[1], h2n, j, r0);
        __syncthreads();

        // output head: out[b, t] = w_lin . h2_new[b] + b_lin  (32 threads, overlapped with L3)
        if (tid < RPB) {
            float s = blin_v;
#pragma unroll 8
            for (int jj = 0; jj < H; jj++) s = fmaf(wlin_s[jj], h2n[jj * RPB + tid], s);
            out[(b0 + tid) * T + t] = s;
        }

        // ----- layer 3 -----
        acc_init(acc, b3);
        gemm80(acc, W3, h2n, j, r0);
        gemm80(acc, W3 + 80 * 80, h3o, j, r0);
        cell(acc, c[2], h3n, j, r0);
        __syncthreads();

        // ----- layer 4 -----
        acc_init(acc, b4);
        gemm80(acc, W4, h3n, j, r0);
        gemm80(acc, W4 + 80 * 80, h4o, j, r0);
        cell(acc, c[3], h4n, j, r0);
        // no end-of-step barrier needed: next consumers of h4n are behind >=2 barriers
    }
}

extern "C" void kernel_launch(void *const *d_in, const int *in_sizes, int n_in,
                              void *d_out, int out_size) {
    const float *input = (const float *)d_in[0];
    const float *wlin  = (const float *)d_in[17];
    const float *blin  = (const float *)d_in[18];

    pack_kernel<<<(WTOT + BTOT + 255) / 256, 256>>>(
        (const float *)d_in[1],  (const float *)d_in[2],  (const float *)d_in[3],  (const float *)d_in[4],
        (const float *)d_in[5],  (const float *)d_in[6],  (const float *)d_in[7],  (const float *)d_in[8],
        (const float *)d_in[9],  (const float *)d_in[10], (const float *)d_in[11], (const float *)d_in[12],
        (const float *)d_in[13], (const float *)d_in[14], (const float *)d_in[15], (const float *)d_in[16]);

    cudaFuncSetAttribute(lstm4_kernel, cudaFuncAttributeMaxDynamicSharedMemorySize, SMEM_BYTES);
    lstm4_kernel<<<NCTA, NTHR, SMEM_BYTES>>>(input, wlin, blin, (float *)d_out);
}

// round 2
// speedup vs baseline: 1.0295x; 1.0295x over previous
#include <cuda_runtime.h>

// Problem constants (fixed by setup_inputs)
#define H   80
#define B   4096
#define T   512
#define RPB 32              // rows (batch) per CTA
#define NCTA (B / RPB)      // 128
#define NTHR 640            // thread = (j in [0,80), rblk in [0,8)), 4 rows each

// Packed weight layout (floats):
//   layer 1: k in [0,81)  : Wp[(k*80+j)*4 + g], k=0 -> x weight, k>=1 -> h1 weight (col k-1)
//   layer l>=2: k in [0,160): k<80 -> w_ih col k (input h_{l-1}), k>=80 -> w_hh col k-80 (own h)
#define OFF1 0
#define OFF2 25920          // 81*320
#define OFF3 77120          // OFF2 + 160*320
#define OFF4 128320
#define WTOT 179520
#define BTOT 1280           // 4 layers * 320 (bias, gate-interleaved [l][j][g])

__device__ float g_Wp[WTOT];
__device__ float g_Bp[BTOT];

typedef unsigned long long u64;

__device__ __forceinline__ u64 dup2(float w) {
    u64 r; unsigned u = __float_as_uint(w);
    asm("mov.b64 %0, {%1, %1};" : "=l"(r) : "r"(u));
    return r;
}
__device__ __forceinline__ void fma2(u64 &d, u64 a, u64 b) {
    asm("fma.rn.f32x2 %0, %1, %2, %0;" : "+l"(d) : "l"(a), "l"(b));
}
__device__ __forceinline__ float lo32(u64 v) { return __uint_as_float((unsigned)v); }
__device__ __forceinline__ float hi32(u64 v) { return __uint_as_float((unsigned)(v >> 32)); }

__device__ __forceinline__ float sigf(float x) {
    return __fdividef(1.0f, 1.0f + __expf(-x));
}
__device__ __forceinline__ float tanh_f(float x) {
    return fmaf(2.0f, sigf(2.0f * x), -1.0f);   // tanh(x) = 2*sigmoid(2x) - 1
}

// One k-slice for 4 rows: 4 gate weights x 4 h values -> 8 FFMA2
// acc layout: acc[2g + p] = gate g, row pair p (rows 2p, 2p+1)
__device__ __forceinline__ void fmak(u64 *acc, float4 w, ulonglong2 ha) {
    u64 w0 = dup2(w.x), w1 = dup2(w.y), w2 = dup2(w.z), w3 = dup2(w.w);
    fma2(acc[0], w0, ha.x); fma2(acc[1], w0, ha.y);
    fma2(acc[2], w1, ha.x); fma2(acc[3], w1, ha.y);
    fma2(acc[4], w2, ha.x); fma2(acc[5], w2, ha.y);
    fma2(acc[6], w3, ha.x); fma2(acc[7], w3, ha.y);
}

// 80-wide dot accumulation, manual 4-chunk so 4 weight LDGs stay in flight
__device__ __forceinline__ void gemm80(u64 *acc, const float4 *__restrict__ W,
                                       const float *__restrict__ hsrc, int j, int r0) {
#pragma unroll
    for (int kk = 0; kk < 80; kk += 4) {
        float4 w0 = W[(kk + 0) * 80 + j];
        float4 w1 = W[(kk + 1) * 80 + j];
        float4 w2 = W[(kk + 2) * 80 + j];
        float4 w3 = W[(kk + 3) * 80 + j];
        ulonglong2 h0 = *(const ulonglong2 *)(hsrc + (kk + 0) * RPB + r0);
        ulonglong2 h1 = *(const ulonglong2 *)(hsrc + (kk + 1) * RPB + r0);
        ulonglong2 h2 = *(const ulonglong2 *)(hsrc + (kk + 2) * RPB + r0);
        ulonglong2 h3 = *(const ulonglong2 *)(hsrc + (kk + 3) * RPB + r0);
        fmak(acc, w0, h0);
        fmak(acc, w1, h1);
        fmak(acc, w2, h2);
        fmak(acc, w3, h3);
    }
}

// LSTM elementwise for 4 rows; c is 4-row cell state in registers
__device__ __forceinline__ void cell(const u64 *acc, float *c, float *hdst, int j, int r0) {
    float hv[4];
#pragma unroll
    for (int qq = 0; qq < 4; qq++) {
        int pp = qq >> 1;
        float iv, fv, gv, ov;
        if (qq & 1) {
            iv = hi32(acc[0 + pp]); fv = hi32(acc[2 + pp]);
            gv = hi32(acc[4 + pp]); ov = hi32(acc[6 + pp]);
        } else {
            iv = lo32(acc[0 + pp]); fv = lo32(acc[2 + pp]);
            gv = lo32(acc[4 + pp]); ov = lo32(acc[6 + pp]);
        }
        float cc = sigf(fv) * c[qq] + sigf(iv) * tanh_f(gv);
        c[qq] = cc;
        hv[qq] = sigf(ov) * tanh_f(cc);
    }
    *(float4 *)(hdst + j * RPB + r0) = make_float4(hv[0], hv[1], hv[2], hv[3]);
}

__device__ __forceinline__ void acc_init(u64 *acc, float4 b) {
    acc[0] = acc[1] = dup2(b.x);
    acc[2] = acc[3] = dup2(b.y);
    acc[4] = acc[5] = dup2(b.z);
    acc[6] = acc[7] = dup2(b.w);
}

// ---------------------------------------------------------------------------
// Weight/bias repack kernel: transpose + gate-interleave into g_Wp / g_Bp
// ---------------------------------------------------------------------------
__global__ void pack_kernel(
    const float *wih1, const float *whh1, const float *bih1, const float *bhh1,
    const float *wih2, const float *whh2, const float *bih2, const float *bhh2,
    const float *wih3, const float *whh3, const float *bih3, const float *bhh3,
    const float *wih4, const float *whh4, const float *bih4, const float *bhh4) {
    int idx = blockIdx.x * blockDim.x + threadIdx.x;
    const float *wih[4] = {wih1, wih2, wih3, wih4};
    const float *whh[4] = {whh1, whh2, whh3, whh4};
    const float *bih[4] = {bih1, bih2, bih3, bih4};
    const float *bhh[4] = {bhh1, bhh2, bhh3, bhh4};
    if (idx < WTOT) {
        int l, off;
        if (idx < OFF2)      { l = 0; off = OFF1; }
        else if (idx < OFF3) { l = 1; off = OFF2; }
        else if (idx < OFF4) { l = 2; off = OFF3; }
        else                 { l = 3; off = OFF4; }
        int e = idx - off;
        int g = e & 3;
        int j = (e >> 2) % 80;
        int k = e / 320;
        int row = g * 80 + j;
        float v;
        if (l == 0) v = (k == 0) ? wih[0][row] : whh[0][row * 80 + (k - 1)];
        else        v = (k < 80) ? wih[l][row * 80 + k] : whh[l][row * 80 + (k - 80)];
        g_Wp[idx] = v;
    } else if (idx < WTOT + BTOT) {
        int e = idx - WTOT;
        int g = e & 3;
        int j = (e >> 2) % 80;
        int l = e / 320;
        int row = g * 80 + j;
        g_Bp[e] = bih[l][row] + bhh[l][row];
    }
}

// ---------------------------------------------------------------------------
// Main persistent LSTM kernel: each CTA owns 32 rows through all layers/steps
// 640 threads: thread (j, rblk) computes gates for unit j on 4 rows.
// ---------------------------------------------------------------------------
#define SMEM_FLOATS (4 * 2 * H * RPB + RPB + H + BTOT)
#define SMEM_BYTES  (SMEM_FLOATS * 4)

__global__ void __launch_bounds__(NTHR, 1) lstm4_kernel(
    const float *__restrict__ input,  // (B, T)
    const float *__restrict__ wlin,   // (80)
    const float *__restrict__ blin,   // (1)
    float *__restrict__ out) {        // (B, T)
    extern __shared__ float sm[];
    float *hs_base = sm;                          // [4][2][80][32]
    float *x_s     = sm + 4 * 2 * H * RPB;        // [32]
    float *wlin_s  = x_s + RPB;                   // [80]
    float *bias_s  = wlin_s + H;                  // [4][80][4] gate-interleaved

    const int tid  = threadIdx.x;
    const int j    = tid % 80;
    const int rblk = tid / 80;                    // 0..7
    const int r0   = rblk * 4;
    const int b0   = blockIdx.x * RPB;

    for (int i = tid; i < 4 * 2 * H * RPB; i += NTHR) hs_base[i] = 0.0f;
    if (tid < H) wlin_s[tid] = wlin[tid];
    for (int i = tid; i < BTOT; i += NTHR) bias_s[i] = g_Bp[i];
    const float blin_v = blin[0];

    float c[4][4];
#pragma unroll
    for (int l = 0; l < 4; l++)
#pragma unroll
        for (int qq = 0; qq < 4; qq++) c[l][qq] = 0.0f;

    const float4 *W1 = (const float4 *)(g_Wp + OFF1);
    const float4 *W2 = (const float4 *)(g_Wp + OFF2);
    const float4 *W3 = (const float4 *)(g_Wp + OFF3);
    const float4 *W4 = (const float4 *)(g_Wp + OFF4);
    const float4 *bias4 = (const float4 *)bias_s;

    __syncthreads();

    for (int t = 0; t < T; t++) {
        const int p = t & 1;       // write buffer this step
        const int q = p ^ 1;       // own-h read buffer (previous step)
        float *h1n = hs_base + (0 * 2 + p) * H * RPB;
        const float *h1o = hs_base + (0 * 2 + q) * H * RPB;
        float *h2n = hs_base + (1 * 2 + p) * H * RPB;
        const float *h2o = hs_base + (1 * 2 + q) * H * RPB;
        float *h3n = hs_base + (2 * 2 + p) * H * RPB;
        const float *h3o = hs_base + (2 * 2 + q) * H * RPB;
        float *h4n = hs_base + (3 * 2 + p) * H * RPB;
        const float *h4o = hs_base + (3 * 2 + q) * H * RPB;

        if (tid < RPB) x_s[tid] = input[(b0 + tid) * T + t];
        __syncthreads();

        u64 acc[8];

        // ----- layer 1 (input: scalar x, own h1) -----
        acc_init(acc, bias4[0 * 80 + j]);
        fmak(acc, W1[j], *(const ulonglong2 *)(x_s + r0));   // k = 0: x weight
        gemm80(acc, W1 + 80, h1o, j, r0);                     // k = 1..80: recurrent
        cell(acc, c[0], h1n, j, r0);
        __syncthreads();

        // ----- layer 2 -----
        acc_init(acc, bias4[1 * 80 + j]);
        gemm80(acc, W2, h1n, j, r0);
        gemm80(acc, W2 + 80 * 80, h2o, j, r0);
        cell(acc, c[1], h2n, j, r0);
        __syncthreads();

        // output head: out[b, t] = w_lin . h2_new[b] + b_lin (32 threads, overlapped with L3)
        if (tid < RPB) {
            float s = blin_v;
#pragma unroll 8
            for (int jj = 0; jj < H; jj++) s = fmaf(wlin_s[jj], h2n[jj * RPB + tid], s);
            out[(b0 + tid) * T + t] = s;
        }

        // ----- layer 3 -----
        acc_init(acc, bias4[2 * 80 + j]);
        gemm80(acc, W3, h2n, j, r0);
        gemm80(acc, W3 + 80 * 80, h3o, j, r0);
        cell(acc, c[2], h3n, j, r0);
        __syncthreads();

        // ----- layer 4 -----
        acc_init(acc, bias4[3 * 80 + j]);
        gemm80(acc, W4, h3n, j, r0);
        gemm80(acc, W4 + 80 * 80, h4o, j, r0);
        cell(acc, c[3], h4n, j, r0);
        // no end-of-step barrier needed: next step's top barrier orders h4n writes
    }
}

extern "C" void kernel_launch(void *const *d_in, const int *in_sizes, int n_in,
                              void *d_out, int out_size) {
    const float *input = (const float *)d_in[0];
    const float *wlin  = (const float *)d_in[17];
    const float *blin  = (const float *)d_in[18];

    pack_kernel<<<(WTOT + BTOT + 255) / 256, 256>>>(
        (const float *)d_in[1],  (const float *)d_in[2],  (const float *)d_in[3],  (const float *)d_in[4],
        (const float *)d_in[5],  (const float *)d_in[6],  (const float *)d_in[7],  (const float *)d_in[8],
        (const float *)d_in[9],  (const float *)d_in[10], (const float *)d_in[11], (const float *)d_in[12],
        (const float *)d_in[13], (const float *)d_in[14], (const float *)d_in[15], (const float *)d_in[16]);

    cudaFuncSetAttribute(lstm4_kernel, cudaFuncAttributeMaxDynamicSharedMemorySize, SMEM_BYTES);
    lstm4_kernel<<<NCTA, NTHR, SMEM_BYTES>>>(input, wlin, blin, (float *)d_out);
}

// round 3
// speedup vs baseline: 1.2064x; 1.1718x over previous
#include <cuda_runtime.h>

// Problem constants (fixed by setup_inputs)
#define H   80
#define B   4096
#define T   512
#define RPB 32              // rows (batch) per CTA
#define NCTA (B / RPB)      // 128
#define NTHR 320            // thread = (j in [0,80), rblk in [0,4)), 8 rows each

// Packed weight layout (floats):
//   layer 1: k in [0,81)  : Wp[(k*80+j)*4 + g], k=0 -> x weight, k>=1 -> h1 weight (col k-1)
//   layer l>=2: k in [0,160): k<80 -> w_ih col k (input h_{l-1}), k>=80 -> w_hh col k-80 (own h)
#define OFF1 0
#define OFF2 25920          // 81*320
#define OFF3 77120          // OFF2 + 160*320
#define OFF4 128320
#define WTOT 179520
#define BTOT 1280           // 4 layers * 320 (bias, gate-interleaved [l][j][g])

__device__ float g_Wp[WTOT];
__device__ float g_Bp[BTOT];

typedef unsigned long long u64;

__device__ __forceinline__ u64 dup2(float w) {
    u64 r; unsigned u = __float_as_uint(w);
    asm("mov.b64 %0, {%1, %1};" : "=l"(r) : "r"(u));
    return r;
}
__device__ __forceinline__ void fma2(u64 &d, u64 a, u64 b) {
    asm("fma.rn.f32x2 %0, %1, %2, %0;" : "+l"(d) : "l"(a), "l"(b));
}
__device__ __forceinline__ float lo32(u64 v) { return __uint_as_float((unsigned)v); }
__device__ __forceinline__ float hi32(u64 v) { return __uint_as_float((unsigned)(v >> 32)); }

__device__ __forceinline__ float sigf(float x) {
    return __fdividef(1.0f, 1.0f + __expf(-x));
}
__device__ __forceinline__ float tanh_f(float x) {
    return fmaf(2.0f, sigf(2.0f * x), -1.0f);   // tanh(x) = 2*sigmoid(2x) - 1
}

// One k-slice for 8 rows: 4 gate weights x 8 h values -> 16 FFMA2
// acc layout: acc[4g + p] = gate g, row pair p (rows 2p, 2p+1)
__device__ __forceinline__ void fmak8(u64 *acc, float4 w, ulonglong2 ha, ulonglong2 hb) {
    u64 w0 = dup2(w.x), w1 = dup2(w.y), w2 = dup2(w.z), w3 = dup2(w.w);
    fma2(acc[0],  w0, ha.x); fma2(acc[1],  w0, ha.y); fma2(acc[2],  w0, hb.x); fma2(acc[3],  w0, hb.y);
    fma2(acc[4],  w1, ha.x); fma2(acc[5],  w1, ha.y); fma2(acc[6],  w1, hb.x); fma2(acc[7],  w1, hb.y);
    fma2(acc[8],  w2, ha.x); fma2(acc[9],  w2, ha.y); fma2(acc[10], w2, hb.x); fma2(acc[11], w2, hb.y);
    fma2(acc[12], w3, ha.x); fma2(acc[13], w3, ha.y); fma2(acc[14], w3, hb.x); fma2(acc[15], w3, hb.y);
}

// Pipelined NK-wide gemm with one-chunk-ahead prefetch of weights (LDG) and h (LDS).
// k < 80 reads hA, k >= 80 reads hB. W is float4[k][80], k in [0, NK).
template<int NK>
__device__ __forceinline__ void gemmN(u64 *acc, const float4 *__restrict__ W,
                                      const float *__restrict__ hA,
                                      const float *__restrict__ hB, int j, int r0) {
    float4     wb[2][4];
    ulonglong2 hb[2][4][2];
#pragma unroll
    for (int q = 0; q < 4; q++) {
        wb[0][q] = W[q * 80 + j];
        const ulonglong2 *hv = (const ulonglong2 *)(hA + q * RPB + r0);
        hb[0][q][0] = hv[0]; hb[0][q][1] = hv[1];
    }
#pragma unroll 4
    for (int kk = 0; kk < NK; kk += 4) {
        const int cur = (kk >> 2) & 1;
        const int nxt = cur ^ 1;
        const int kn  = kk + 4;
        if (kn < NK) {
            const float *hp = (kn < 80) ? hA : hB;
            const int    ho = (kn < 80) ? kn : (kn - 80);
#pragma unroll
            for (int q = 0; q < 4; q++) {
                wb[nxt][q] = W[(kn + q) * 80 + j];
                const ulonglong2 *hv = (const ulonglong2 *)(hp + (ho + q) * RPB + r0);
                hb[nxt][q][0] = hv[0]; hb[nxt][q][1] = hv[1];
            }
        }
#pragma unroll
        for (int q = 0; q < 4; q++)
            fmak8(acc, wb[cur][q], hb[cur][q][0], hb[cur][q][1]);
    }
}

// LSTM elementwise for 8 rows; c is 8-row cell state in registers
__device__ __forceinline__ void cell(const u64 *acc, float *c, float *hdst, int j, int r0) {
    float hv[8];
#pragma unroll
    for (int qq = 0; qq < 8; qq++) {
        int pp = qq >> 1;
        float iv, fv, gv, ov;
        if (qq & 1) {
            iv = hi32(acc[0 + pp]); fv = hi32(acc[4 + pp]);
            gv = hi32(acc[8 + pp]); ov = hi32(acc[12 + pp]);
        } else {
            iv = lo32(acc[0 + pp]); fv = lo32(acc[4 + pp]);
            gv = lo32(acc[8 + pp]); ov = lo32(acc[12 + pp]);
        }
        float cc = sigf(fv) * c[qq] + sigf(iv) * tanh_f(gv);
        c[qq] = cc;
        hv[qq] = sigf(ov) * tanh_f(cc);
    }
    float4 *d = (float4 *)(hdst + j * RPB + r0);
    d[0] = make_float4(hv[0], hv[1], hv[2], hv[3]);
    d[1] = make_float4(hv[4], hv[5], hv[6], hv[7]);
}

__device__ __forceinline__ void acc_init(u64 *acc, float4 b) {
    u64 b0 = dup2(b.x), b1 = dup2(b.y), b2 = dup2(b.z), b3 = dup2(b.w);
#pragma unroll
    for (int p = 0; p < 4; p++) { acc[0 + p] = b0; acc[4 + p] = b1; acc[8 + p] = b2; acc[12 + p] = b3; }
}

// ---------------------------------------------------------------------------
// Weight/bias repack kernel: transpose + gate-interleave into g_Wp / g_Bp
// ---------------------------------------------------------------------------
__global__ void pack_kernel(
    const float *wih1, const float *whh1, const float *bih1, const float *bhh1,
    const float *wih2, const float *whh2, const float *bih2, const float *bhh2,
    const float *wih3, const float *whh3, const float *bih3, const float *bhh3,
    const float *wih4, const float *whh4, const float *bih4, const float *bhh4) {
    int idx = blockIdx.x * blockDim.x + threadIdx.x;
    const float *wih[4] = {wih1, wih2, wih3, wih4};
    const float *whh[4] = {whh1, whh2, whh3, whh4};
    const float *bih[4] = {bih1, bih2, bih3, bih4};
    const float *bhh[4] = {bhh1, bhh2, bhh3, bhh4};
    if (idx < WTOT) {
        int l, off;
        if (idx < OFF2)      { l = 0; off = OFF1; }
        else if (idx < OFF3) { l = 1; off = OFF2; }
        else if (idx < OFF4) { l = 2; off = OFF3; }
        else                 { l = 3; off = OFF4; }
        int e = idx - off;
        int g = e & 3;
        int j = (e >> 2) % 80;
        int k = e / 320;
        int row = g * 80 + j;
        float v;
        if (l == 0) v = (k == 0) ? wih[0][row] : whh[0][row * 80 + (k - 1)];
        else        v = (k < 80) ? wih[l][row * 80 + k] : whh[l][row * 80 + (k - 80)];
        g_Wp[idx] = v;
    } else if (idx < WTOT + BTOT) {
        int e = idx - WTOT;
        int g = e & 3;
        int j = (e >> 2) % 80;
        int l = e / 320;
        int row = g * 80 + j;
        g_Bp[e] = bih[l][row] + bhh[l][row];
    }
}

// ---------------------------------------------------------------------------
// Main persistent LSTM kernel: each CTA owns 32 rows through all layers/steps
// ---------------------------------------------------------------------------
#define SMEM_FLOATS (4 * 2 * H * RPB + RPB + H + BTOT)
#define SMEM_BYTES  (SMEM_FLOATS * 4)

__global__ void __launch_bounds__(NTHR, 1) lstm4_kernel(
    const float *__restrict__ input,  // (B, T)
    const float *__restrict__ wlin,   // (80)
    const float *__restrict__ blin,   // (1)
    float *__restrict__ out) {        // (B, T)
    extern __shared__ float sm[];
    float *hs_base = sm;                          // [4][2][80][32]
    float *x_s     = sm + 4 * 2 * H * RPB;        // [32]
    float *wlin_s  = x_s + RPB;                   // [80]
    float *bias_s  = wlin_s + H;                  // [4][80][4] gate-interleaved

    const int tid  = threadIdx.x;
    const int j    = tid % 80;
    const int rblk = tid / 80;                    // 0..3
    const int r0   = rblk * 8;
    const int b0   = blockIdx.x * RPB;

    for (int i = tid; i < 4 * 2 * H * RPB; i += NTHR) hs_base[i] = 0.0f;
    if (tid < H) wlin_s[tid] = wlin[tid];
    for (int i = tid; i < BTOT; i += NTHR) bias_s[i] = g_Bp[i];
    const float blin_v = blin[0];

    float c[4][8];
#pragma unroll
    for (int l = 0; l < 4; l++)
#pragma unroll
        for (int qq = 0; qq < 8; qq++) c[l][qq] = 0.0f;

    const float4 *W1 = (const float4 *)(g_Wp + OFF1);
    const float4 *W2 = (const float4 *)(g_Wp + OFF2);
    const float4 *W3 = (const float4 *)(g_Wp + OFF3);
    const float4 *W4 = (const float4 *)(g_Wp + OFF4);
    const float4 *bias4 = (const float4 *)bias_s;

    __syncthreads();

    for (int t = 0; t < T; t++) {
        const int p = t & 1;       // write buffer this step
        const int q = p ^ 1;       // own-h read buffer (previous step)
        float *h1n = hs_base + (0 * 2 + p) * H * RPB;
        const float *h1o = hs_base + (0 * 2 + q) * H * RPB;
        float *h2n = hs_base + (1 * 2 + p) * H * RPB;
        const float *h2o = hs_base + (1 * 2 + q) * H * RPB;
        float *h3n = hs_base + (2 * 2 + p) * H * RPB;
        const float *h3o = hs_base + (2 * 2 + q) * H * RPB;
        float *h4n = hs_base + (3 * 2 + p) * H * RPB;
        const float *h4o = hs_base + (3 * 2 + q) * H * RPB;

        if (tid < RPB) x_s[tid] = input[(b0 + tid) * T + t];
        __syncthreads();

        u64 acc[16];

        // ----- layer 1 (input: scalar x, own h1) -----
        acc_init(acc, bias4[0 * 80 + j]);
        {
            const ulonglong2 *xv = (const ulonglong2 *)(x_s + r0);
            fmak8(acc, W1[j], xv[0], xv[1]);   // k = 0: x weight
        }
        gemmN<80>(acc, W1 + 80, h1o, h1o, j, r0);   // k = 1..80: recurrent
        cell(acc, c[0], h1n, j, r0);
        __syncthreads();

        // ----- layer 2 (fused 160-wide gemm: input h1n, own h2o) -----
        acc_init(acc, bias4[1 * 80 + j]);
        gemmN<160>(acc, W2, h1n, h2o, j, r0);
        cell(acc, c[1], h2n, j, r0);
        __syncthreads();

        // output head: out[b, t] = w_lin . h2_new[b] + b_lin (32 threads, overlapped with L3)
        if (tid < RPB) {
            float s = blin_v;
#pragma unroll 8
            for (int jj = 0; jj < H; jj++) s = fmaf(wlin_s[jj], h2n[jj * RPB + tid], s);
            out[(b0 + tid) * T + t] = s;
        }

        // ----- layer 3 -----
        acc_init(acc, bias4[2 * 80 + j]);
        gemmN<160>(acc, W3, h2n, h3o, j, r0);
        cell(acc, c[2], h3n, j, r0);
        __syncthreads();

        // ----- layer 4 -----
        acc_init(acc, bias4[3 * 80 + j]);
        gemmN<160>(acc, W4, h3n, h4o, j, r0);
        cell(acc, c[3], h4n, j, r0);
        // no end-of-step barrier needed: next step's top barrier orders h4n writes
    }
}

extern "C" void kernel_launch(void *const *d_in, const int *in_sizes, int n_in,
                              void *d_out, int out_size) {
    const float *input = (const float *)d_in[0];
    const float *wlin  = (const float *)d_in[17];
    const float *blin  = (const float *)d_in[18];

    pack_kernel<<<(WTOT + BTOT + 255) / 256, 256>>>(
        (const float *)d_in[1],  (const float *)d_in[2],  (const float *)d_in[3],  (const float *)d_in[4],
        (const float *)d_in[5],  (const float *)d_in[6],  (const float *)d_in[7],  (const float *)d_in[8],
        (const float *)d_in[9],  (const float *)d_in[10], (const float *)d_in[11], (const float *)d_in[12],
        (const float *)d_in[13], (const float *)d_in[14], (const float *)d_in[15], (const float *)d_in[16]);

    cudaFuncSetAttribute(lstm4_kernel, cudaFuncAttributeMaxDynamicSharedMemorySize, SMEM_BYTES);
    lstm4_kernel<<<NCTA, NTHR, SMEM_BYTES>>>(input, wlin, blin, (float *)d_out);
}